// round 1
// baseline (speedup 1.0000x reference)
#include <cuda_runtime.h>
#include <math.h>

namespace {

constexpr int NLOC = 1024;
constexpr int NNEI = 128;
constexpr int NG2  = 32;
constexpr int NH   = 4;
constexpr int KPAD = 36;   // padded row for ks / g2v (16B-aligned, de-conflicted writes)
constexpr int APAD = 129;  // padded row for A: bank = (qi + k) % 32, conflict-free

struct Smem {
  float wqkT[256 * 32];      // [col][c]  (transposed w_qk)   32 KB
  float wvT [128 * 32];      // [col][c]  (transposed w_v)    16 KB
  float whs [128 * 32];      // [gh][c]   (w_head as-is)      16 KB
  float ks  [NNEI * KPAD];   // K rows, current head          18 KB
  float g2v [NNEI * KPAD];   // V rows, current head          18 KB
  float h2s [NNEI * 4];      // h2 rows (padded)               2 KB
  float sws [NNEI];
  float msk [NNEI];
  float bh  [NG2];
  float A   [NNEI * APAD];   // per-thread-private attn row   66 KB
};

__global__ void __launch_bounds__(128, 1)
rep_kernel(const float* __restrict__ g2,   const float* __restrict__ h2,
           const float* __restrict__ sw,   const float* __restrict__ wqk,
           const float* __restrict__ wv,   const float* __restrict__ wh,
           const float* __restrict__ bhead,const float* __restrict__ weq,
           const int*   __restrict__ nmask,float* __restrict__ out)
{
  extern __shared__ float smem_raw[];
  Smem& s = *reinterpret_cast<Smem*>(smem_raw);
  const int i  = blockIdx.x;
  const int qi = threadIdx.x;

  // ---- cooperative staging of weights (transposed for broadcast float4 reads) ----
  for (int idx = qi; idx < 256 * 32; idx += 128) {
    int col = idx >> 5, c = idx & 31;
    s.wqkT[idx] = wqk[c * 256 + col];
  }
  for (int idx = qi; idx < 128 * 32; idx += 128) {
    int col = idx >> 5, c = idx & 31;
    s.wvT[idx] = wv[c * 128 + col];
  }
  for (int idx = qi; idx < 128 * 32; idx += 128) s.whs[idx] = wh[idx];

  float h2q0, h2q1, h2q2, swq, maskq;
  {
    const float* h2r = h2 + ((long)i * NNEI + qi) * 3;
    h2q0 = h2r[0]; h2q1 = h2r[1]; h2q2 = h2r[2];
    s.h2s[qi * 4 + 0] = h2q0; s.h2s[qi * 4 + 1] = h2q1;
    s.h2s[qi * 4 + 2] = h2q2; s.h2s[qi * 4 + 3] = 0.f;
    swq = sw[(long)i * NNEI + qi];
    s.sws[qi] = swq;
    maskq = nmask[(long)i * NNEI + qi] ? 1.f : 0.f;
    s.msk[qi] = maskq;
    if (qi < NG2) s.bh[qi] = bhead[qi];
  }

  // own g2 row -> registers
  float g2r[32];
  {
    const float* gp = g2 + ((long)i * NNEI + qi) * NG2;
    #pragma unroll
    for (int c = 0; c < 32; c += 4) {
      float4 v = *reinterpret_cast<const float4*>(gp + c);
      g2r[c] = v.x; g2r[c+1] = v.y; g2r[c+2] = v.z; g2r[c+3] = v.w;
    }
  }
  __syncthreads();

  float g2o[32];
  #pragma unroll
  for (int c = 0; c < 32; ++c) g2o[c] = 0.f;
  float h2o0 = 0.f, h2o1 = 0.f, h2o2 = 0.f;

  #pragma unroll 1
  for (int h = 0; h < NH; ++h) {
    // ---- projections: q (regs), k (smem), v (smem) for this head ----
    float q[32];
    #pragma unroll
    for (int d = 0; d < 32; ++d) {
      const float4* wq = reinterpret_cast<const float4*>(&s.wqkT[(8 * d + h) * 32]);
      const float4* wk = reinterpret_cast<const float4*>(&s.wqkT[(8 * d + 4 + h) * 32]);
      float aq = 0.f, ak = 0.f;
      #pragma unroll
      for (int c4 = 0; c4 < 8; ++c4) {
        float4 vq = wq[c4], vk = wk[c4];
        aq += g2r[4*c4]*vq.x + g2r[4*c4+1]*vq.y + g2r[4*c4+2]*vq.z + g2r[4*c4+3]*vq.w;
        ak += g2r[4*c4]*vk.x + g2r[4*c4+1]*vk.y + g2r[4*c4+2]*vk.z + g2r[4*c4+3]*vk.w;
      }
      q[d] = aq;
      s.ks[qi * KPAD + d] = ak;
    }
    #pragma unroll 2
    for (int g = 0; g < 32; ++g) {
      const float4* wvp = reinterpret_cast<const float4*>(&s.wvT[(g * 4 + h) * 32]);
      float a = 0.f;
      #pragma unroll
      for (int c4 = 0; c4 < 8; ++c4) {
        float4 v = wvp[c4];
        a += g2r[4*c4]*v.x + g2r[4*c4+1]*v.y + g2r[4*c4+2]*v.z + g2r[4*c4+3]*v.w;
      }
      s.g2v[qi * KPAD + g] = a;
    }
    __syncthreads();

    // ---- A row: (q.k / sqrt(nd)) * h2ht, shifted-sw, row max ----
    float rmax = -1e30f;
    #pragma unroll 4
    for (int k = 0; k < NNEI; ++k) {
      const float4* kr = reinterpret_cast<const float4*>(&s.ks[k * KPAD]);
      float acc = 0.f;
      #pragma unroll
      for (int d4 = 0; d4 < 8; ++d4) {
        float4 v = kr[d4];
        acc += q[4*d4]*v.x + q[4*d4+1]*v.y + q[4*d4+2]*v.z + q[4*d4+3]*v.w;
      }
      float h2ht = h2q0 * s.h2s[k*4] + h2q1 * s.h2s[k*4+1] + h2q2 * s.h2s[k*4+2];
      float a = acc * 0.17677669529663689f * h2ht;   // 1/sqrt(32)
      a = (a + 20.f) * (swq * s.sws[k]) - 20.f;
      s.A[qi * APAD + k] = a;
      rmax = fmaxf(rmax, a);
    }

    // ---- softmax (full row, as in reference: mask applied AFTER softmax) ----
    float rsum = 0.f;
    #pragma unroll 4
    for (int k = 0; k < NNEI; ++k) {
      float e = __expf(s.A[qi * APAD + k] - rmax);
      s.A[qi * APAD + k] = e;
      rsum += e;
    }
    const float rinv  = 1.f / rsum;
    const float weqh  = weq[h];
    const float cbase = rinv * maskq * swq * 0.57735026918962576f;  // 1/sqrt(3)

    // ---- coefficient pass (fused with out_h accumulation) ----
    #pragma unroll 4
    for (int k = 0; k < NNEI; ++k) {
      float h2k0 = s.h2s[k*4], h2k1 = s.h2s[k*4+1], h2k2 = s.h2s[k*4+2];
      float h2ht = h2q0*h2k0 + h2q1*h2k1 + h2q2*h2k2;
      float coef = s.A[qi * APAD + k] * cbase * s.msk[k] * s.sws[k] * h2ht;
      s.A[qi * APAD + k] = coef;
      float c2 = coef * weqh;
      h2o0 += c2 * h2k0; h2o1 += c2 * h2k1; h2o2 += c2 * h2k2;
    }

    // ---- out_g = A @ g2v  (broadcast float4 over g2v rows) ----
    float og[32];
    #pragma unroll
    for (int g = 0; g < 32; ++g) og[g] = 0.f;
    #pragma unroll 2
    for (int k = 0; k < NNEI; ++k) {
      float a = s.A[qi * APAD + k];
      const float4* gv = reinterpret_cast<const float4*>(&s.g2v[k * KPAD]);
      #pragma unroll
      for (int g4 = 0; g4 < 8; ++g4) {
        float4 v = gv[g4];
        og[4*g4]   += a * v.x; og[4*g4+1] += a * v.y;
        og[4*g4+2] += a * v.z; og[4*g4+3] += a * v.w;
      }
    }

    // ---- fold this head into g2_out via w_head rows (gh = g*4 + h) ----
    #pragma unroll
    for (int g = 0; g < 32; ++g) {
      float v = og[g];
      const float4* whr = reinterpret_cast<const float4*>(&s.whs[(g * 4 + h) * 32]);
      #pragma unroll
      for (int c4 = 0; c4 < 8; ++c4) {
        float4 w = whr[c4];
        g2o[4*c4]   += v * w.x; g2o[4*c4+1] += v * w.y;
        g2o[4*c4+2] += v * w.z; g2o[4*c4+3] += v * w.w;
      }
    }
    __syncthreads();
  }

  // ---- write outputs: g2_out then h2_out (concatenated) ----
  {
    float* gout = out + ((long)i * NNEI + qi) * NG2;
    #pragma unroll
    for (int c = 0; c < 32; c += 4) {
      float4 o;
      o.x = g2o[c]   + s.bh[c];
      o.y = g2o[c+1] + s.bh[c+1];
      o.z = g2o[c+2] + s.bh[c+2];
      o.w = g2o[c+3] + s.bh[c+3];
      *reinterpret_cast<float4*>(gout + c) = o;
    }
    float* hout = out + (long)NLOC * NNEI * NG2 + ((long)i * NNEI + qi) * 3;
    hout[0] = h2o0; hout[1] = h2o1; hout[2] = h2o2;
  }
}

} // namespace

extern "C" void kernel_launch(void* const* d_in, const int* in_sizes, int n_in,
                              void* d_out, int out_size) {
  const float* g2    = (const float*)d_in[0];
  const float* h2    = (const float*)d_in[1];
  const float* sw    = (const float*)d_in[2];
  const float* wqk   = (const float*)d_in[3];
  const float* wv    = (const float*)d_in[4];
  const float* wh    = (const float*)d_in[5];
  const float* bh    = (const float*)d_in[6];
  const float* weq   = (const float*)d_in[7];
  const int*   nmask = (const int*)d_in[8];
  float* out = (float*)d_out;

  // idempotent, capture-safe (not a stream op, no allocation)
  cudaFuncSetAttribute(rep_kernel, cudaFuncAttributeMaxDynamicSharedMemorySize,
                       (int)sizeof(Smem));
  rep_kernel<<<NLOC, NNEI, sizeof(Smem)>>>(g2, h2, sw, wqk, wv, wh, bh, weq, nmask, out);
}

// round 2
// speedup vs baseline: 1.7703x; 1.7703x over previous
#include <cuda_runtime.h>

namespace {

typedef unsigned long long ull;

constexpr int NLOC = 1024;
constexpr int NNEI = 128;
constexpr int NG2  = 32;
constexpr int NH   = 4;
constexpr int KPAD = 36;   // 144B row stride, 16B aligned

// byte offsets into dynamic smem
constexpr unsigned OFF_WQK = 0;        // 8192 floats (w_qk transposed [col][c])
constexpr unsigned OFF_WV  = 32768;    // 4096 floats (w_v transposed [col][c])
constexpr unsigned OFF_WH  = 49152;    // 4096 floats (w_head [gh][c])
constexpr unsigned OFF_KS  = 65536;    // 128*36 floats (K rows, current head)
constexpr unsigned OFF_GV  = 83968;    // 128*36 floats (V rows, current head)
constexpr unsigned OFF_H2  = 102400;   // 128*4 floats
constexpr unsigned OFF_SW  = 104448;   // 128 floats (sw)
constexpr unsigned OFF_PK  = 104960;   // 128 floats (mask*sw)
constexpr unsigned OFF_BH  = 105472;   // 32 floats
constexpr unsigned SMEM_BYTES = 105600;

__device__ __forceinline__ ull ffma2(ull a, ull b, ull c) {
  ull d; asm("fma.rn.f32x2 %0, %1, %2, %3;" : "=l"(d) : "l"(a), "l"(b), "l"(c)); return d;
}
__device__ __forceinline__ ull fadd2(ull a, ull b) {
  ull d; asm("add.rn.f32x2 %0, %1, %2;" : "=l"(d) : "l"(a), "l"(b)); return d;
}
__device__ __forceinline__ ull pack2(float x, float y) {
  ull r; asm("mov.b64 %0, {%1, %2};" : "=l"(r) : "f"(x), "f"(y)); return r;
}
__device__ __forceinline__ float2 unpack2(ull a) {
  float x, y; asm("mov.b64 {%0, %1}, %2;" : "=f"(x), "=f"(y) : "l"(a));
  return make_float2(x, y);
}
// 16-byte shared load as two packed f32x2 (one LDS.128)
__device__ __forceinline__ void lds4(ull& a, ull& b, unsigned addr) {
  asm("ld.shared.v2.b64 {%0, %1}, [%2];" : "=l"(a), "=l"(b) : "r"(addr));
}

__global__ void __launch_bounds__(128, 2)
rep_kernel(const float* __restrict__ g2,    const float* __restrict__ h2,
           const float* __restrict__ sw,    const float* __restrict__ wqk,
           const float* __restrict__ wv,    const float* __restrict__ wh,
           const float* __restrict__ bhead, const float* __restrict__ weq,
           const int*   __restrict__ nmask, float* __restrict__ out)
{
  extern __shared__ float smf[];
  const unsigned sb = (unsigned)__cvta_generic_to_shared(smf);
  const int i  = blockIdx.x;
  const int qi = threadIdx.x;

  // ---- stage weights (transposed so hot loops read rows as packed f32x2) ----
  for (int idx = qi; idx < 256 * 32; idx += 128) {
    int col = idx >> 5, c = idx & 31;
    smf[(OFF_WQK >> 2) + idx] = wqk[c * 256 + col];
  }
  for (int idx = qi; idx < 128 * 32; idx += 128) {
    int col = idx >> 5, c = idx & 31;
    smf[(OFF_WV >> 2) + idx] = wv[c * 128 + col];
  }
  for (int idx = qi; idx < 128 * 32; idx += 128)
    smf[(OFF_WH >> 2) + idx] = wh[idx];

  float h2q0, h2q1, h2q2, swq, maskq;
  {
    const float* h2r = h2 + ((long)i * NNEI + qi) * 3;
    h2q0 = h2r[0]; h2q1 = h2r[1]; h2q2 = h2r[2];
    smf[(OFF_H2 >> 2) + qi * 4 + 0] = h2q0;
    smf[(OFF_H2 >> 2) + qi * 4 + 1] = h2q1;
    smf[(OFF_H2 >> 2) + qi * 4 + 2] = h2q2;
    smf[(OFF_H2 >> 2) + qi * 4 + 3] = 0.f;
    swq = sw[(long)i * NNEI + qi];
    smf[(OFF_SW >> 2) + qi] = swq;
    maskq = nmask[(long)i * NNEI + qi] ? 1.f : 0.f;
    smf[(OFF_PK >> 2) + qi] = maskq * swq;      // post-softmax per-k factor
    if (qi < NG2) smf[(OFF_BH >> 2) + qi] = bhead[qi];
  }

  float w_eq[NH];
  #pragma unroll
  for (int h = 0; h < NH; ++h) w_eq[h] = weq[h];

  // own g2 row, packed as f32x2 pairs
  ull g2p[16];
  {
    const float* gp = g2 + ((long)i * NNEI + qi) * NG2;
    #pragma unroll
    for (int t = 0; t < 16; ++t) {
      float2 v = *reinterpret_cast<const float2*>(gp + 2 * t);
      g2p[t] = pack2(v.x, v.y);
    }
  }
  __syncthreads();

  ull g2o2[16];                 // g2_out accumulator (32 channels, packed)
  #pragma unroll
  for (int t = 0; t < 16; ++t) g2o2[t] = 0ull;
  float h2a0 = 0.f, h2a1 = 0.f, h2a2 = 0.f;

  #pragma unroll 1
  for (int h = 0; h < NH; ++h) {
    // ================= projections =================
    ull q2[16];
    #pragma unroll 2
    for (int d2 = 0; d2 < 16; ++d2) {       // two d values per iteration
      float qv[2];
      #pragma unroll
      for (int half = 0; half < 2; ++half) {
        int d = 2 * d2 + half;
        unsigned rq = sb + OFF_WQK + (unsigned)((8 * d + h) * 128);
        unsigned rk = sb + OFF_WQK + (unsigned)((8 * d + 4 + h) * 128);
        ull aq0 = 0, aq1 = 0, ak0 = 0, ak1 = 0;
        #pragma unroll
        for (int j = 0; j < 4; ++j) {
          ull p0, p1, p2, p3;
          lds4(p0, p1, rq + j * 32);
          lds4(p2, p3, rq + j * 32 + 16);
          aq0 = ffma2(g2p[4 * j + 0], p0, aq0);
          aq1 = ffma2(g2p[4 * j + 1], p1, aq1);
          aq0 = ffma2(g2p[4 * j + 2], p2, aq0);
          aq1 = ffma2(g2p[4 * j + 3], p3, aq1);
        }
        #pragma unroll
        for (int j = 0; j < 4; ++j) {
          ull p0, p1, p2, p3;
          lds4(p0, p1, rk + j * 32);
          lds4(p2, p3, rk + j * 32 + 16);
          ak0 = ffma2(g2p[4 * j + 0], p0, ak0);
          ak1 = ffma2(g2p[4 * j + 1], p1, ak1);
          ak0 = ffma2(g2p[4 * j + 2], p2, ak0);
          ak1 = ffma2(g2p[4 * j + 3], p3, ak1);
        }
        float2 fq = unpack2(fadd2(aq0, aq1));
        float2 fk = unpack2(fadd2(ak0, ak1));
        qv[half] = fq.x + fq.y;
        smf[(OFF_KS >> 2) + qi * KPAD + d] = fk.x + fk.y;
      }
      // fold 1/sqrt(nd) into q
      q2[d2] = pack2(qv[0] * 0.17677669529663689f, qv[1] * 0.17677669529663689f);
    }
    // v projection
    #pragma unroll 2
    for (int g = 0; g < 32; ++g) {
      unsigned rv = sb + OFF_WV + (unsigned)((g * 4 + h) * 128);
      ull a0 = 0, a1 = 0;
      #pragma unroll
      for (int j = 0; j < 4; ++j) {
        ull p0, p1, p2, p3;
        lds4(p0, p1, rv + j * 32);
        lds4(p2, p3, rv + j * 32 + 16);
        a0 = ffma2(g2p[4 * j + 0], p0, a0);
        a1 = ffma2(g2p[4 * j + 1], p1, a1);
        a0 = ffma2(g2p[4 * j + 2], p2, a0);
        a1 = ffma2(g2p[4 * j + 3], p3, a1);
      }
      float2 f = unpack2(fadd2(a0, a1));
      smf[(OFF_GV >> 2) + qi * KPAD + g] = f.x + f.y;
    }
    __syncthreads();

    // ================= single-pass attention over k =================
    // No max-subtraction: gated logits are bounded (|a| << 88), exp is safe.
    ull og2[16];
    #pragma unroll
    for (int t = 0; t < 16; ++t) og2[t] = 0ull;
    float h2o0 = 0.f, h2o1 = 0.f, h2o2 = 0.f;
    float rsum = 0.f;

    #pragma unroll 2
    for (int k = 0; k < NNEI; ++k) {
      unsigned ka = sb + OFF_KS + (unsigned)(k * (KPAD * 4));
      ull a0 = 0, a1 = 0, a2 = 0, a3 = 0;
      #pragma unroll
      for (int j = 0; j < 4; ++j) {
        ull p0, p1, p2, p3;
        lds4(p0, p1, ka + j * 32);
        lds4(p2, p3, ka + j * 32 + 16);
        a0 = ffma2(q2[4 * j + 0], p0, a0);
        a1 = ffma2(q2[4 * j + 1], p1, a1);
        a2 = ffma2(q2[4 * j + 2], p2, a2);
        a3 = ffma2(q2[4 * j + 3], p3, a3);
      }
      float2 fr = unpack2(fadd2(fadd2(a0, a1), fadd2(a2, a3)));
      float dot = fr.x + fr.y;                       // q.k / sqrt(nd) (scale in q)

      float4 h2k = *reinterpret_cast<const float4*>(&smf[(OFF_H2 >> 2) + 4 * k]);
      float h2ht = fmaf(h2q0, h2k.x, fmaf(h2q1, h2k.y, h2q2 * h2k.z));

      float a = dot * h2ht;
      float swk = smf[(OFF_SW >> 2) + k];
      a = fmaf(a + 20.f, swq * swk, -20.f);
      float e = __expf(a);
      rsum += e;

      float w = e * smf[(OFF_PK >> 2) + k] * h2ht;   // e * mask_k*sw_k * h2ht
      h2o0 = fmaf(w, h2k.x, h2o0);
      h2o1 = fmaf(w, h2k.y, h2o1);
      h2o2 = fmaf(w, h2k.z, h2o2);

      ull w2 = pack2(w, w);
      unsigned ga = sb + OFF_GV + (unsigned)(k * (KPAD * 4));
      #pragma unroll
      for (int j = 0; j < 4; ++j) {
        ull p0, p1, p2, p3;
        lds4(p0, p1, ga + j * 32);
        lds4(p2, p3, ga + j * 32 + 16);
        og2[4 * j + 0] = ffma2(w2, p0, og2[4 * j + 0]);
        og2[4 * j + 1] = ffma2(w2, p1, og2[4 * j + 1]);
        og2[4 * j + 2] = ffma2(w2, p2, og2[4 * j + 2]);
        og2[4 * j + 3] = ffma2(w2, p3, og2[4 * j + 3]);
      }
    }

    // normalization + remaining query-side constants
    const float sfin = (1.f / rsum) * maskq * swq * 0.57735026918962576f; // /sqrt(3)
    const float heq  = sfin * w_eq[h];
    h2a0 = fmaf(h2o0, heq, h2a0);
    h2a1 = fmaf(h2o1, heq, h2a1);
    h2a2 = fmaf(h2o2, heq, h2a2);

    // fold this head through w_head rows (gh = g*4 + h)
    #pragma unroll 2
    for (int t = 0; t < 16; ++t) {
      float2 f = unpack2(og2[t]);
      #pragma unroll
      for (int half = 0; half < 2; ++half) {
        int g = 2 * t + half;
        float v = (half ? f.y : f.x) * sfin;
        ull v2 = pack2(v, v);
        unsigned rw = sb + OFF_WH + (unsigned)((g * 4 + h) * 128);
        #pragma unroll
        for (int j = 0; j < 4; ++j) {
          ull p0, p1, p2, p3;
          lds4(p0, p1, rw + j * 32);
          lds4(p2, p3, rw + j * 32 + 16);
          g2o2[4 * j + 0] = ffma2(v2, p0, g2o2[4 * j + 0]);
          g2o2[4 * j + 1] = ffma2(v2, p1, g2o2[4 * j + 1]);
          g2o2[4 * j + 2] = ffma2(v2, p2, g2o2[4 * j + 2]);
          g2o2[4 * j + 3] = ffma2(v2, p3, g2o2[4 * j + 3]);
        }
      }
    }
    __syncthreads();   // before next head overwrites ks/g2v
  }

  // ---- write outputs: g2_out then h2_out (concatenated) ----
  {
    float* gout = out + ((long)i * NNEI + qi) * NG2;
    #pragma unroll
    for (int t = 0; t < 16; t += 2) {
      float2 f0 = unpack2(g2o2[t]);
      float2 f1 = unpack2(g2o2[t + 1]);
      float4 o;
      o.x = f0.x + smf[(OFF_BH >> 2) + 2 * t + 0];
      o.y = f0.y + smf[(OFF_BH >> 2) + 2 * t + 1];
      o.z = f1.x + smf[(OFF_BH >> 2) + 2 * t + 2];
      o.w = f1.y + smf[(OFF_BH >> 2) + 2 * t + 3];
      *reinterpret_cast<float4*>(gout + 2 * t) = o;
    }
    float* hout = out + (long)NLOC * NNEI * NG2 + ((long)i * NNEI + qi) * 3;
    hout[0] = h2a0; hout[1] = h2a1; hout[2] = h2a2;
  }
}

} // namespace

extern "C" void kernel_launch(void* const* d_in, const int* in_sizes, int n_in,
                              void* d_out, int out_size) {
  const float* g2    = (const float*)d_in[0];
  const float* h2    = (const float*)d_in[1];
  const float* sw    = (const float*)d_in[2];
  const float* wqk   = (const float*)d_in[3];
  const float* wv    = (const float*)d_in[4];
  const float* wh    = (const float*)d_in[5];
  const float* bh    = (const float*)d_in[6];
  const float* weq   = (const float*)d_in[7];
  const int*   nmask = (const int*)d_in[8];
  float* out = (float*)d_out;

  cudaFuncSetAttribute(rep_kernel, cudaFuncAttributeMaxDynamicSharedMemorySize,
                       (int)SMEM_BYTES);
  rep_kernel<<<NLOC, NNEI, SMEM_BYTES>>>(g2, h2, sw, wqk, wv, wh, bh, weq, nmask, out);
}